// round 12
// baseline (speedup 1.0000x reference)
#include <cuda_runtime.h>
#include <cuda_bf16.h>

#define EPSV 1e-8f
#define TPB 128
#define WARPS 4
#define EPT 4                    // elements per thread
#define WELEMS (32 * EPT)        // 128 elements per warp tile

__global__ void __launch_bounds__(TPB)
cov3d_kernel(const float4* __restrict__ quat,   // N x 4
             const float*  __restrict__ scale,  // N x 3
             float* __restrict__ out,           // N x 9
             int n)
{
    // Separate scale and output staging (no reuse hazard between them):
    // scale: 128*3 floats = 1536 B/warp;  out: 128*9 floats = 4608 B/warp.
    __shared__ __align__(16) float s_scale[WARPS][WELEMS * 3];
    __shared__ __align__(16) float s_out[WARPS][WELEMS * 9];

    const int warp = threadIdx.x >> 5;
    const int lane = threadIdx.x & 31;

    const int gw = blockIdx.x * WARPS + warp;   // global warp id
    const int nw = gridDim.x * WARPS;           // total warps
    const int ntiles = (n + WELEMS - 1) / WELEMS;

    float* sbuf = s_scale[warp];
    float* obuf = s_out[warp];

    // ---- prologue: prefetch first tile (full tiles only; partial handled in-loop)
    int t = gw;
    float4 q[EPT];
    float4 scr[3];
    bool full = (t < ntiles) && ((t + 1) * WELEMS <= n);
    if (full) {
        const float4* qp = quat + (size_t)t * WELEMS;
        #pragma unroll
        for (int e = 0; e < EPT; e++) q[e] = __ldcs(qp + e * 32 + lane);
        const float4* sp4 = (const float4*)(scale + (size_t)t * WELEMS * 3);
        #pragma unroll
        for (int k = 0; k < 3; k++) scr[k] = __ldcs(sp4 + k * 32 + lane);
    }

    for (; t < ntiles; t += nw) {
        const int base = t * WELEMS;
        const int wrem = min(WELEMS, n - base);

        // ---- stage current tile's scale into smem ----
        if (full) {
            float4* b4 = (float4*)sbuf;
            #pragma unroll
            for (int k = 0; k < 3; k++) b4[k * 32 + lane] = scr[k];
        } else {
            // partial tile: load directly (no prefetch was issued for it)
            #pragma unroll
            for (int e = 0; e < EPT; e++) {
                int li = e * 32 + lane;
                if (li < wrem) q[e] = __ldcs(quat + base + li);
            }
            const float* sp = scale + (size_t)base * 3;
            for (int j = lane; j < wrem * 3; j += 32)
                sbuf[j] = __ldcs(sp + j);
        }
        __syncwarp();

        // ---- read per-element scales (stride-3: conflict-free) ----
        float sc[EPT][3];
        #pragma unroll
        for (int e = 0; e < EPT; e++) {
            int li = e * 32 + lane;
            if (li < wrem) {
                sc[e][0] = sbuf[li * 3 + 0];
                sc[e][1] = sbuf[li * 3 + 1];
                sc[e][2] = sbuf[li * 3 + 2];
            }
        }

        // ---- prefetch NEXT tile now: 7 LDG.128 in flight across compute+store
        const int tn = t + nw;
        const bool nfull = (tn < ntiles) && ((tn + 1) * WELEMS <= n);
        float4 qn[EPT];
        float4 scrn[3];
        if (nfull) {
            const float4* qp = quat + (size_t)tn * WELEMS;
            #pragma unroll
            for (int e = 0; e < EPT; e++) qn[e] = __ldcs(qp + e * 32 + lane);
            const float4* sp4 = (const float4*)(scale + (size_t)tn * WELEMS * 3);
            #pragma unroll
            for (int k = 0; k < 3; k++) scrn[k] = __ldcs(sp4 + k * 32 + lane);
        }

        // ---- compute + stage outputs (stride-9 smem: conflict-free) ----
        #pragma unroll
        for (int e = 0; e < EPT; e++) {
            int li = e * 32 + lane;
            if (li >= wrem) continue;

            float w = q[e].x, x = q[e].y, y = q[e].z, z = q[e].w;

            float s0 = fabsf(sc[e][0]) + EPSV;
            float s1 = fabsf(sc[e][1]) + EPSV;
            float s2 = fabsf(sc[e][2]) + EPSV;
            float s0sq = s0 * s0, s1sq = s1 * s1, s2sq = s2 * s2;

            // Rotation with 1/||q||^2 folded in (R entries quadratic in q).
            float ww = w * w, xx = x * x, yy = y * y, zz = z * z;
            float inv = 1.0f / (ww + xx + yy + zz);
            float xy = x * y, xz = x * z, yz = y * z;
            float wx = w * x, wy = w * y, wz = w * z;

            float r00 = (ww + xx - yy - zz) * inv;
            float r01 = 2.0f * (xy - wz) * inv;
            float r02 = 2.0f * (xz + wy) * inv;
            float r10 = 2.0f * (xy + wz) * inv;
            float r11 = (ww - xx + yy - zz) * inv;
            float r12 = 2.0f * (yz - wx) * inv;
            float r20 = 2.0f * (xz - wy) * inv;
            float r21 = 2.0f * (yz + wx) * inv;
            float r22 = (ww - xx - yy + zz) * inv;

            // M = R diag(s^2) R^T (symmetric)
            float m00 = s0sq*r00*r00 + s1sq*r01*r01 + s2sq*r02*r02;
            float m01 = s0sq*r00*r10 + s1sq*r01*r11 + s2sq*r02*r12;
            float m02 = s0sq*r00*r20 + s1sq*r01*r21 + s2sq*r02*r22;
            float m11 = s0sq*r10*r10 + s1sq*r11*r11 + s2sq*r12*r12;
            float m12 = s0sq*r10*r20 + s1sq*r11*r21 + s2sq*r12*r22;
            float m22 = s0sq*r20*r20 + s1sq*r21*r21 + s2sq*r22*r22;

            float* o = obuf + li * 9;
            o[0] = m00; o[1] = m01; o[2] = m02;
            o[3] = m01; o[4] = m11; o[5] = m12;
            o[6] = m02; o[7] = m12; o[8] = m22;
        }
        __syncwarp();

        // ---- flush: coalesced float4 streaming stores (288 float4/warp) ----
        if (wrem == WELEMS) {
            float4* o4 = (float4*)(out + (size_t)base * 9);
            const float4* b4 = (const float4*)obuf;
            #pragma unroll
            for (int k = 0; k < 9; k++)
                __stcs(o4 + k * 32 + lane, b4[k * 32 + lane]);
        } else {
            float* og = out + (size_t)base * 9;
            for (int j = lane; j < wrem * 9; j += 32)
                __stcs(og + j, obuf[j]);
        }
        __syncwarp();   // obuf/sbuf safe to reuse next iteration

        // ---- rotate pipeline registers ----
        #pragma unroll
        for (int e = 0; e < EPT; e++) q[e] = qn[e];
        #pragma unroll
        for (int k = 0; k < 3; k++) scr[k] = scrn[k];
        full = nfull;
    }
}

extern "C" void kernel_launch(void* const* d_in, const int* in_sizes, int n_in,
                              void* d_out, int out_size)
{
    const float4* quat  = (const float4*)d_in[0];  // N x 4 float32
    const float*  scale = (const float*) d_in[1];  // N x 3 float32
    float* out = (float*)d_out;                    // N x 3 x 3 float32

    int n = in_sizes[0] / 4;
    int ntiles = (n + WELEMS - 1) / WELEMS;
    int max_blocks = (ntiles + WARPS - 1) / WARPS;
    int blocks = 1480;                              // persistent: ~5 tiles/warp
    if (blocks > max_blocks) blocks = max_blocks;
    cov3d_kernel<<<blocks, TPB>>>(quat, scale, out, n);
}

// round 13
// speedup vs baseline: 1.0007x; 1.0007x over previous
#include <cuda_runtime.h>
#include <cuda_bf16.h>

#define EPSV 1e-8f
#define TPB 256
#define WARPS 8
#define EPT 4                    // elements per thread
#define WELEMS (32 * EPT)        // 128 elements per warp tile

__global__ void __launch_bounds__(TPB)
cov3d_kernel(const float4* __restrict__ quat,   // N x 4
             const float*  __restrict__ scale,  // N x 3
             float* __restrict__ out,           // N x 9
             int n)
{
    // One private region per warp: 128 elems * 9 floats = 1152 floats (4608 B).
    // Reused: first 384 floats hold staged scale, then overwritten by outputs.
    __shared__ __align__(16) float s_buf[WARPS][WELEMS * 9];

    const int warp = threadIdx.x >> 5;
    const int lane = threadIdx.x & 31;

    const int base = (blockIdx.x * WARPS + warp) * WELEMS;  // warp's first elem
    if (base < n) {                                          // warp-uniform
        const int wrem = min(WELEMS, n - base);
        float* buf = s_buf[warp];

        // ---- batch quaternion loads (4 independent LDG.128, streaming) ----
        float4 q[EPT];
        #pragma unroll
        for (int e = 0; e < EPT; e++) {
            int li = e * 32 + lane;
            if (li < wrem) q[e] = __ldcs(quat + base + li);
        }

        // ---- stage scale coalesced into smem (3 more LDG.128, streaming) ----
        if (wrem == WELEMS) {
            const float4* sp4 = (const float4*)(scale + (size_t)base * 3);
            float4* b4 = (float4*)buf;
            #pragma unroll
            for (int k = 0; k < 3; k++)
                b4[lane + k * 32] = __ldcs(sp4 + lane + k * 32);
        } else {
            const float* sp = scale + (size_t)base * 3;
            for (int j = lane; j < wrem * 3; j += 32)
                buf[j] = __ldcs(sp + j);
        }
        __syncwarp();

        // ---- read per-element scales (stride-3 smem: conflict-free) ----
        float sc[EPT][3];
        #pragma unroll
        for (int e = 0; e < EPT; e++) {
            int li = e * 32 + lane;
            if (li < wrem) {
                sc[e][0] = buf[li * 3 + 0];
                sc[e][1] = buf[li * 3 + 1];
                sc[e][2] = buf[li * 3 + 2];
            }
        }
        __syncwarp();   // scale reads done before buf is reused for outputs

        // ---- compute + stage outputs (stride-9 smem writes: conflict-free) ----
        #pragma unroll
        for (int e = 0; e < EPT; e++) {
            int li = e * 32 + lane;
            if (li >= wrem) continue;

            float w = q[e].x, x = q[e].y, y = q[e].z, z = q[e].w;

            float s0 = fabsf(sc[e][0]) + EPSV;
            float s1 = fabsf(sc[e][1]) + EPSV;
            float s2 = fabsf(sc[e][2]) + EPSV;
            float s0sq = s0 * s0, s1sq = s1 * s1, s2sq = s2 * s2;

            // Rotation with 1/||q||^2 folded in (R entries quadratic in q).
            float ww = w * w, xx = x * x, yy = y * y, zz = z * z;
            float inv = 1.0f / (ww + xx + yy + zz);
            float xy = x * y, xz = x * z, yz = y * z;
            float wx = w * x, wy = w * y, wz = w * z;

            float r00 = (ww + xx - yy - zz) * inv;
            float r01 = 2.0f * (xy - wz) * inv;
            float r02 = 2.0f * (xz + wy) * inv;
            float r10 = 2.0f * (xy + wz) * inv;
            float r11 = (ww - xx + yy - zz) * inv;
            float r12 = 2.0f * (yz - wx) * inv;
            float r20 = 2.0f * (xz - wy) * inv;
            float r21 = 2.0f * (yz + wx) * inv;
            float r22 = (ww - xx - yy + zz) * inv;

            // M = R diag(s^2) R^T (symmetric)
            float m00 = s0sq*r00*r00 + s1sq*r01*r01 + s2sq*r02*r02;
            float m01 = s0sq*r00*r10 + s1sq*r01*r11 + s2sq*r02*r12;
            float m02 = s0sq*r00*r20 + s1sq*r01*r21 + s2sq*r02*r22;
            float m11 = s0sq*r10*r10 + s1sq*r11*r11 + s2sq*r12*r12;
            float m12 = s0sq*r10*r20 + s1sq*r11*r21 + s2sq*r12*r22;
            float m22 = s0sq*r20*r20 + s1sq*r21*r21 + s2sq*r22*r22;

            float* o = buf + li * 9;
            o[0] = m00; o[1] = m01; o[2] = m02;
            o[3] = m01; o[4] = m11; o[5] = m12;
            o[6] = m02; o[7] = m12; o[8] = m22;
        }
        __syncwarp();

        // ---- flush: coalesced float4 DEFAULT (write-back) stores ----
        // L2 is 126 MB; let the output park in L2 and drain lazily instead of
        // forcing in-kernel writeback with .cs (which was on the critical path).
        if (wrem == WELEMS) {
            float4* o4 = (float4*)(out + (size_t)base * 9);
            const float4* b4 = (const float4*)buf;
            #pragma unroll
            for (int k = 0; k < 9; k++)
                o4[lane + k * 32] = b4[lane + k * 32];
        } else {
            float* og = out + (size_t)base * 9;
            for (int j = lane; j < wrem * 9; j += 32)
                og[j] = buf[j];
        }
    }
}

extern "C" void kernel_launch(void* const* d_in, const int* in_sizes, int n_in,
                              void* d_out, int out_size)
{
    const float4* quat  = (const float4*)d_in[0];  // N x 4 float32
    const float*  scale = (const float*) d_in[1];  // N x 3 float32
    float* out = (float*)d_out;                    // N x 3 x 3 float32

    int n = in_sizes[0] / 4;
    int elems_per_block = TPB * EPT;               // 1024
    int blocks = (n + elems_per_block - 1) / elems_per_block;
    cov3d_kernel<<<blocks, TPB>>>(quat, scale, out, n);
}